// round 10
// baseline (speedup 1.0000x reference)
#include <cuda_runtime.h>
#include <cuda_fp16.h>
#include <cstdint>

#define HW 128
#define CC 64
#define BBATCH 32
#define KK 1000
#define LL 12
#define OO 24

// h activations, NHWC fp32: [B][H][W][C] = 128 MB
__device__ float g_h[BBATCH * HW * HW * CC];
// fp16 weights, padded rows: [tap(9)][co(64)][144 B] (72 fp16 slots, 64 used)
__device__ unsigned char g_wt[9 * 9216];

// ===================== small helpers =====================
__device__ __forceinline__ uint32_t smem_u32(const void* p) {
    uint32_t a;
    asm("{ .reg .u64 t; cvta.to.shared.u64 t, %1; cvt.u32.u64 %0, t; }" : "=r"(a) : "l"(p));
    return a;
}
__device__ __forceinline__ unsigned long long ffma2(unsigned long long a,
                                                    unsigned long long b,
                                                    unsigned long long c) {
    unsigned long long d;
    asm("fma.rn.f32x2 %0, %1, %2, %3;" : "=l"(d) : "l"(a), "l"(b), "l"(c));
    return d;
}
__device__ __forceinline__ unsigned long long addf2(unsigned long long a, unsigned long long b) {
    unsigned long long d;
    asm("add.rn.f32x2 %0, %1, %2;" : "=l"(d) : "l"(a), "l"(b));
    return d;
}
__device__ __forceinline__ unsigned long long pack2(float lo, float hi) {
    unsigned long long d;
    asm("mov.b64 %0, {%1, %2};" : "=l"(d) : "f"(lo), "f"(hi));
    return d;
}
__device__ __forceinline__ void unpack2(unsigned long long v, float& lo, float& hi) {
    asm("mov.b64 {%0, %1}, %2;" : "=f"(lo), "=f"(hi) : "l"(v));
}
__device__ __forceinline__ void ldsm4(uint32_t* r, uint32_t a) {
    asm volatile("ldmatrix.sync.aligned.m8n8.x4.shared.b16 {%0,%1,%2,%3}, [%4];"
                 : "=r"(r[0]), "=r"(r[1]), "=r"(r[2]), "=r"(r[3]) : "r"(a));
}
__device__ __forceinline__ void mma16816h(float* d, const uint32_t* a, uint32_t b0, uint32_t b1) {
    asm volatile("mma.sync.aligned.m16n8k16.row.col.f32.f16.f16.f32 "
                 "{%0,%1,%2,%3}, {%4,%5,%6,%7}, {%8,%9}, {%0,%1,%2,%3};"
                 : "+f"(d[0]), "+f"(d[1]), "+f"(d[2]), "+f"(d[3])
                 : "r"(a[0]), "r"(a[1]), "r"(a[2]), "r"(a[3]), "r"(b0), "r"(b1));
}

// ===================== conv smem layout (dynamic) =====================
#define ASTRIDE 144
#define ATILE (130 * 144)        // 18,720 B per input-row slab (fp16)
#define BTILE (64 * 144)         // 9,216 B per tap
#define SM_B 0                   // 3 tiles for current dy: 27,648 B
#define SM_A 27648               // 4 slabs: 74,880 B -> ends 102,528
#define SM_BIAS 102528           // 64 floats
#define SM_TOT 102784

// ============================================================================
// Prep: convert conv_w to fp16, write padded [n=co][k=ci] tiles per tap.
// ============================================================================
__global__ void wprep_kernel(const float* __restrict__ w) {
    int idx = blockIdx.x * 256 + threadIdx.x;
    if (idx >= CC * CC * 9) return;
    int co = idx / 576;
    int rem = idx - co * 576;
    int ci = rem / 9;
    int tap = rem - ci * 9;                 // dy*3 + dx
    *reinterpret_cast<__half*>(g_wt + tap * BTILE + co * ASTRIDE + ci * 2) =
        __float2half(w[idx]);
}

// ============================================================================
// Conv via mma.sync fp16 single-pass. CTA = (2 rows, image b), 8 warps.
// __launch_bounds__(256, 2): cap regs at 128 -> 2 CTAs/SM so one CTA's
// staging overlaps the other's MMA stream.
// ============================================================================
__global__ __launch_bounds__(256, 2) void conv_tc_kernel(
    const float* __restrict__ x,     // [B][C][H][W]
    const float* __restrict__ bias)  // [C]
{
    extern __shared__ unsigned char smem[];
    const uint32_t sb = smem_u32(smem);
    const int t = threadIdx.x;
    const int lane = t & 31;
    const int w = t >> 5;
    const int y0 = blockIdx.x * 2;
    const int b = blockIdx.y;
    const int orow = w >> 2;
    const int pxl = (w & 3) * 32;

    if (t < 64) *reinterpret_cast<float*>(smem + SM_BIAS + t * 4) = bias[t];

    for (int i = t; i < 4 * 128; i += 256) {
        int slab = i >> 7;
        int rem = i & 127;
        int row = (rem >> 6) ? 129 : 0;
        int ci = rem & 63;
        *reinterpret_cast<uint16_t*>(smem + SM_A + slab * ATILE + row * ASTRIDE + ci * 2) = 0;
    }

    for (int i = t; i < 4 * CC * HW; i += 256) {
        int px = i & 127;
        int ci = (i >> 7) & 63;
        int r = i >> 13;
        int yin = y0 - 1 + r;
        float f = 0.f;
        if ((unsigned)yin < 128u)
            f = x[((size_t)(b * CC + ci) * HW + yin) * HW + px];
        *reinterpret_cast<__half*>(smem + SM_A + r * ATILE + (px + 1) * ASTRIDE + ci * 2) =
            __float2half(f);
    }

    const uint32_t aLaneOff = (uint32_t)((lane & 15) * ASTRIDE + (lane >> 4) * 16);
    const uint32_t bLaneOff = (uint32_t)((((lane & 7) + ((lane >> 4) << 3)) * ASTRIDE) +
                                         ((lane >> 3) & 1) * 16);

    float acc[2][8][4];
#pragma unroll
    for (int mt = 0; mt < 2; ++mt)
#pragma unroll
        for (int nt = 0; nt < 8; ++nt)
#pragma unroll
            for (int q = 0; q < 4; ++q) acc[mt][nt][q] = 0.f;

    for (int dy = 0; dy < 3; ++dy) {
        __syncthreads();
        {
            const float4* src = reinterpret_cast<const float4*>(g_wt + dy * 3 * BTILE);
            float4* dst = reinterpret_cast<float4*>(smem + SM_B);
            for (int i = t; i < 3 * BTILE / 16; i += 256) dst[i] = src[i];
        }
        __syncthreads();

        const uint32_t sA = sb + SM_A + (uint32_t)(orow + dy) * ATILE;

#pragma unroll
        for (int ks = 0; ks < 4; ++ks) {
#pragma unroll
            for (int dx = 0; dx < 3; ++dx) {
                uint32_t bf[4][4];
                const uint32_t bBase = sb + SM_B + (uint32_t)dx * BTILE + ks * 32 + bLaneOff;
#pragma unroll
                for (int np = 0; np < 4; ++np)
                    ldsm4(bf[np], bBase + np * 16 * ASTRIDE);
                uint32_t af[2][4];
#pragma unroll
                for (int mt = 0; mt < 2; ++mt) {
                    const uint32_t arow = (uint32_t)(pxl + mt * 16 + dx);
                    ldsm4(af[mt], sA + arow * ASTRIDE + ks * 32 + aLaneOff);
                }
#pragma unroll
                for (int mt = 0; mt < 2; ++mt)
#pragma unroll
                    for (int np = 0; np < 4; ++np) {
                        mma16816h(acc[mt][2 * np],     af[mt], bf[np][0], bf[np][1]);
                        mma16816h(acc[mt][2 * np + 1], af[mt], bf[np][2], bf[np][3]);
                    }
            }
        }
    }

    const float* sbias = reinterpret_cast<const float*>(smem + SM_BIAS);
    const int y = y0 + orow;
    const int cq = (lane & 3) * 2;
    const int pxq = lane >> 2;
#pragma unroll
    for (int mt = 0; mt < 2; ++mt) {
#pragma unroll
        for (int half = 0; half < 2; ++half) {
            int px = pxl + mt * 16 + pxq + half * 8;
            float* dst = g_h + (((size_t)(b * HW) + y) * HW + px) * CC;
#pragma unroll
            for (int nt = 0; nt < 8; ++nt) {
                int co = nt * 8 + cq;
                float a0 = acc[mt][nt][half * 2 + 0] + sbias[co];
                float a1 = acc[mt][nt][half * 2 + 1] + sbias[co + 1];
                a0 = a0 > 0.f ? a0 : 0.02f * a0;
                a1 = a1 > 0.f ? a1 : 0.02f * a1;
                *reinterpret_cast<float2*>(dst + co) = make_float2(a0, a1);
            }
        }
    }
}

// ============================================================================
// Gather + FC v4: block per k, warp per 4 b's, prefetch depth 2.
// ============================================================================
__global__ __launch_bounds__(256) void gather_fc_kernel(
    const int* __restrict__ pos,     // [K][B][L][2] (x, y)
    const float* __restrict__ pw,    // [24][768]
    const float* __restrict__ pb,    // [24]
    float* __restrict__ out)         // [K][B][24]
{
    __shared__ float wsm[384 * 26];  // 39,936 B

    const int t = threadIdx.x;
    const int lane = t & 31;
    const int w = t >> 5;
    const int k = blockIdx.x;
    const int b0 = w * 4;

    const int2* __restrict__ pos2 = reinterpret_cast<const int2*>(pos);

    unsigned long long acc[4][12];
#pragma unroll
    for (int bi = 0; bi < 4; ++bi)
#pragma unroll
        for (int op = 0; op < 12; ++op) acc[bi][op] = 0ULL;

    // hbuf[p mod 3][jj*4 + bi]
    float hbuf[3][8];

    for (int half = 0; half < 2; ++half) {
        __syncthreads();
        for (int i = t; i < 24 * 384; i += 256) {
            int o = i / 384;
            int jl = i - o * 384;
            wsm[jl * 26 + o] = pw[o * 768 + half * 384 + jl];
        }
        __syncthreads();

        // prefetch blocks 0 and 1
#pragma unroll
        for (int pp0 = 0; pp0 < 2; ++pp0) {
            const int l = half * 6 + pp0;
#pragma unroll
            for (int bi = 0; bi < 4; ++bi) {
                const int b = b0 + bi;
                int2 pp = pos2[(k * BBATCH + b) * LL + l];
                int px = pp.x < 0 ? 0 : (pp.x > 127 ? 127 : pp.x);
                int py = pp.y < 0 ? 0 : (pp.y > 127 ? 127 : pp.y);
                const float* hp = &g_h[(((size_t)(b * HW) + py) * HW + px) * CC + lane];
                hbuf[pp0][bi]     = hp[0];
                hbuf[pp0][4 + bi] = hp[32];
            }
        }

#pragma unroll
        for (int p = 0; p < 6; ++p) {
            // prefetch block p+2
            if (p < 4) {
                const int l = half * 6 + p + 2;
                const int slot = (p + 2) % 3;
#pragma unroll
                for (int bi = 0; bi < 4; ++bi) {
                    const int b = b0 + bi;
                    int2 pp = pos2[(k * BBATCH + b) * LL + l];
                    int px = pp.x < 0 ? 0 : (pp.x > 127 ? 127 : pp.x);
                    int py = pp.y < 0 ? 0 : (pp.y > 127 ? 127 : pp.y);
                    const float* hp = &g_h[(((size_t)(b * HW) + py) * HW + px) * CC + lane];
                    hbuf[slot][bi]     = hp[0];
                    hbuf[slot][4 + bi] = hp[32];
                }
            }
            // consume block p: j24 = 2p (c 0..31) and 2p+1 (c 32..63)
            const int slot = p % 3;
#pragma unroll
            for (int jj = 0; jj < 2; ++jj) {
                const int j24 = 2 * p + jj;
                const float2* wrow =
                    reinterpret_cast<const float2*>(&wsm[(j24 * 32 + lane) * 26]);
                float2 wv[12];
#pragma unroll
                for (int op = 0; op < 12; ++op) wv[op] = wrow[op];
#pragma unroll
                for (int bi = 0; bi < 4; ++bi) {
                    float hv = hbuf[slot][jj * 4 + bi];
                    unsigned long long hv2 = pack2(hv, hv);
#pragma unroll
                    for (int op = 0; op < 12; ++op)
                        acc[bi][op] = ffma2(pack2(wv[op].x, wv[op].y), hv2, acc[bi][op]);
                }
            }
        }
    }

    // butterfly reduce over lanes (packed f32x2 adds)
#pragma unroll
    for (int bi = 0; bi < 4; ++bi)
#pragma unroll
        for (int op = 0; op < 12; ++op) {
            unsigned long long v = acc[bi][op];
#pragma unroll
            for (int m = 16; m > 0; m >>= 1) {
                double o = __shfl_xor_sync(0xffffffffu, __longlong_as_double((long long)v), m);
                v = addf2(v, (unsigned long long)__double_as_longlong(o));
            }
            acc[bi][op] = v;
        }

    // lane op (0..11) writes output pair (2op, 2op+1) for each of its 4 b's
#pragma unroll
    for (int bi = 0; bi < 4; ++bi) {
#pragma unroll
        for (int op = 0; op < 12; ++op) {
            if (lane == op) {
                float a0, a1;
                unpack2(acc[bi][op], a0, a1);
                float2 o2;
                o2.x = a0 + pb[2 * op];
                o2.y = a1 + pb[2 * op + 1];
                *reinterpret_cast<float2*>(&out[(size_t)((k * BBATCH + b0 + bi) * OO) + 2 * op]) = o2;
            }
        }
    }
}

// ============================================================================
extern "C" void kernel_launch(void* const* d_in, const int* in_sizes, int n_in,
                              void* d_out, int out_size) {
    const float* x   = (const float*)d_in[0];   // [32][64][128][128]
    const int*   pos = (const int*)  d_in[1];   // [1000][32][12][2]
    const float* cw  = (const float*)d_in[2];   // [64][64][3][3]
    const float* cb  = (const float*)d_in[3];   // [64]
    const float* pw  = (const float*)d_in[4];   // [24][768]
    const float* pb  = (const float*)d_in[5];   // [24]
    float* out = (float*)d_out;                 // [1000][32][24]

    cudaFuncSetAttribute(conv_tc_kernel, cudaFuncAttributeMaxDynamicSharedMemorySize, SM_TOT);

    wprep_kernel<<<(CC * CC * 9 + 255) / 256, 256>>>(cw);
    conv_tc_kernel<<<dim3(HW / 2, BBATCH), 256, SM_TOT>>>(x, cb);
    gather_fc_kernel<<<KK, 256>>>(pos, pw, pb, out);
}

// round 11
// speedup vs baseline: 1.0018x; 1.0018x over previous
#include <cuda_runtime.h>
#include <cuda_fp16.h>
#include <cstdint>

#define HW 128
#define CC 64
#define BBATCH 32
#define KK 1000
#define LL 12
#define OO 24

// h activations, NHWC fp32: [B][H][W][C] = 128 MB
__device__ float g_h[BBATCH * HW * HW * CC];

// ===================== small helpers =====================
__device__ __forceinline__ uint32_t smem_u32(const void* p) {
    uint32_t a;
    asm("{ .reg .u64 t; cvta.to.shared.u64 t, %1; cvt.u32.u64 %0, t; }" : "=r"(a) : "l"(p));
    return a;
}
__device__ __forceinline__ unsigned long long ffma2(unsigned long long a,
                                                    unsigned long long b,
                                                    unsigned long long c) {
    unsigned long long d;
    asm("fma.rn.f32x2 %0, %1, %2, %3;" : "=l"(d) : "l"(a), "l"(b), "l"(c));
    return d;
}
__device__ __forceinline__ unsigned long long addf2(unsigned long long a, unsigned long long b) {
    unsigned long long d;
    asm("add.rn.f32x2 %0, %1, %2;" : "=l"(d) : "l"(a), "l"(b));
    return d;
}
__device__ __forceinline__ unsigned long long pack2(float lo, float hi) {
    unsigned long long d;
    asm("mov.b64 %0, {%1, %2};" : "=l"(d) : "f"(lo), "f"(hi));
    return d;
}
__device__ __forceinline__ void unpack2(unsigned long long v, float& lo, float& hi) {
    asm("mov.b64 {%0, %1}, %2;" : "=f"(lo), "=f"(hi) : "l"(v));
}
__device__ __forceinline__ void ldsm4(uint32_t* r, uint32_t a) {
    asm volatile("ldmatrix.sync.aligned.m8n8.x4.shared.b16 {%0,%1,%2,%3}, [%4];"
                 : "=r"(r[0]), "=r"(r[1]), "=r"(r[2]), "=r"(r[3]) : "r"(a));
}
__device__ __forceinline__ void mma16816h(float* d, const uint32_t* a, uint32_t b0, uint32_t b1) {
    asm volatile("mma.sync.aligned.m16n8k16.row.col.f32.f16.f16.f32 "
                 "{%0,%1,%2,%3}, {%4,%5,%6,%7}, {%8,%9}, {%0,%1,%2,%3};"
                 : "+f"(d[0]), "+f"(d[1]), "+f"(d[2]), "+f"(d[3])
                 : "r"(a[0]), "r"(a[1]), "r"(a[2]), "r"(a[3]), "r"(b0), "r"(b1));
}
__device__ __forceinline__ uint32_t h2u(__half2 h) {
    return *reinterpret_cast<uint32_t*>(&h);
}

// ===================== conv smem layout (dynamic) =====================
#define ASTRIDE 144
#define ATILE (130 * 144)        // 18,720 B per input-row slab (fp16)
#define BTILE (64 * 144)         // 9,216 B per (dy,dx) tap tile
#define SM_B 0                   // 3 dx tiles for current dy: 27,648 B
#define SM_A 27648               // 4 slabs: 74,880 B -> ends 102,528
#define SM_BIAS 102528           // 64 floats
#define SM_TOT 102784

// ============================================================================
// Conv via mma.sync fp16 single-pass. CTA = (2 rows, image b), 8 warps.
// Weight conversion fp32->fp16 folded into per-dy B staging (no wprep kernel).
// A staging vectorized: LDG.128 x8 + STS.128 x4 per item, conflict-free.
// ============================================================================
__global__ __launch_bounds__(256) void conv_tc_kernel(
    const float* __restrict__ x,     // [B][C][H][W]
    const float* __restrict__ cw,    // [Cout][Cin][3][3]
    const float* __restrict__ bias)  // [C]
{
    extern __shared__ unsigned char smem[];
    const uint32_t sb = smem_u32(smem);
    const int t = threadIdx.x;
    const int lane = t & 31;
    const int w = t >> 5;
    const int y0 = blockIdx.x * 2;
    const int b = blockIdx.y;
    const int orow = w >> 2;
    const int pxl = (w & 3) * 32;

    if (t < 64) *reinterpret_cast<float*>(smem + SM_BIAS + t * 4) = bias[t];

    // zero horizontal halo rows (px=-1 -> row 0, px=128 -> row 129) of 4 slabs
    for (int i = t; i < 4 * 2 * 9; i += 256) {
        int slab = i / 18;
        int rem = i - slab * 18;
        int row = (rem >= 9) ? 129 : 0;
        int q = (rem >= 9) ? rem - 9 : rem;   // 9 x 16B covers 144 B row
        *reinterpret_cast<uint4*>(smem + SM_A + slab * ATILE + row * ASTRIDE + q * 16) =
            make_uint4(0, 0, 0, 0);
    }

    // stage A: 4 input rows (y0-1 .. y0+2) -> [px][ci] fp16 slabs, vectorized.
    // item = (r, pxq, oct): 8x LDG.128 (ci octet, 4 px), 4x STS.128.
    for (int i = t; i < 1024; i += 256) {
        int oct = i & 7;
        int pxq = (i >> 3) & 31;
        int r = i >> 8;
        int yin = y0 - 1 + r;
        uint32_t sbase = sb + SM_A + r * ATILE + (pxq * 4 + 1) * ASTRIDE + oct * 16;
        if ((unsigned)yin < 128u) {
            float4 v0, v1, v2, v3, v4, v5, v6, v7;
            const float* xp = x + ((size_t)(b * CC + oct * 8) * HW + yin) * HW + pxq * 4;
            const size_t cs = (size_t)HW * HW;
            v0 = *reinterpret_cast<const float4*>(xp);
            v1 = *reinterpret_cast<const float4*>(xp + cs);
            v2 = *reinterpret_cast<const float4*>(xp + 2 * cs);
            v3 = *reinterpret_cast<const float4*>(xp + 3 * cs);
            v4 = *reinterpret_cast<const float4*>(xp + 4 * cs);
            v5 = *reinterpret_cast<const float4*>(xp + 5 * cs);
            v6 = *reinterpret_cast<const float4*>(xp + 6 * cs);
            v7 = *reinterpret_cast<const float4*>(xp + 7 * cs);
#define STORE_PX(cmp, pi) do { \
            uint4 ov; \
            ov.x = h2u(__floats2half2_rn(v0.cmp, v1.cmp)); \
            ov.y = h2u(__floats2half2_rn(v2.cmp, v3.cmp)); \
            ov.z = h2u(__floats2half2_rn(v4.cmp, v5.cmp)); \
            ov.w = h2u(__floats2half2_rn(v6.cmp, v7.cmp)); \
            asm volatile("st.shared.v4.b32 [%0], {%1,%2,%3,%4};" \
                :: "r"(sbase + (pi) * ASTRIDE), "r"(ov.x), "r"(ov.y), "r"(ov.z), "r"(ov.w)); \
        } while (0)
            STORE_PX(x, 0);
            STORE_PX(y, 1);
            STORE_PX(z, 2);
            STORE_PX(w, 3);
#undef STORE_PX
        } else {
#pragma unroll
            for (int pi = 0; pi < 4; ++pi)
                asm volatile("st.shared.v4.b32 [%0], {%1,%1,%1,%1};"
                             :: "r"(sbase + pi * ASTRIDE), "r"(0u));
        }
    }

    const uint32_t aLaneOff = (uint32_t)((lane & 15) * ASTRIDE + (lane >> 4) * 16);
    const uint32_t bLaneOff = (uint32_t)((((lane & 7) + ((lane >> 4) << 3)) * ASTRIDE) +
                                         ((lane >> 3) & 1) * 16);

    float acc[2][8][4];
#pragma unroll
    for (int mt = 0; mt < 2; ++mt)
#pragma unroll
        for (int nt = 0; nt < 8; ++nt)
#pragma unroll
            for (int q = 0; q < 4; ++q) acc[mt][nt][q] = 0.f;

    for (int dy = 0; dy < 3; ++dy) {
        __syncthreads();
        // stage weights for this dy: convert fp32 -> fp16 into 3 dx tiles
        for (int i = t; i < 4096; i += 256) {
            int co = i >> 6, ci = i & 63;
            const float* wp = cw + co * 576 + ci * 9 + dy * 3;
            unsigned char* basep = smem + SM_B + co * ASTRIDE + ci * 2;
            *reinterpret_cast<__half*>(basep) = __float2half(wp[0]);
            *reinterpret_cast<__half*>(basep + BTILE) = __float2half(wp[1]);
            *reinterpret_cast<__half*>(basep + 2 * BTILE) = __float2half(wp[2]);
        }
        __syncthreads();

        const uint32_t sA = sb + SM_A + (uint32_t)(orow + dy) * ATILE;

#pragma unroll
        for (int ks = 0; ks < 4; ++ks) {
#pragma unroll
            for (int dx = 0; dx < 3; ++dx) {
                uint32_t bf[4][4];
                const uint32_t bBase = sb + SM_B + (uint32_t)dx * BTILE + ks * 32 + bLaneOff;
#pragma unroll
                for (int np = 0; np < 4; ++np)
                    ldsm4(bf[np], bBase + np * 16 * ASTRIDE);
                uint32_t af[2][4];
#pragma unroll
                for (int mt = 0; mt < 2; ++mt) {
                    const uint32_t arow = (uint32_t)(pxl + mt * 16 + dx);
                    ldsm4(af[mt], sA + arow * ASTRIDE + ks * 32 + aLaneOff);
                }
#pragma unroll
                for (int mt = 0; mt < 2; ++mt)
#pragma unroll
                    for (int np = 0; np < 4; ++np) {
                        mma16816h(acc[mt][2 * np],     af[mt], bf[np][0], bf[np][1]);
                        mma16816h(acc[mt][2 * np + 1], af[mt], bf[np][2], bf[np][3]);
                    }
            }
        }
    }

    const float* sbias = reinterpret_cast<const float*>(smem + SM_BIAS);
    const int y = y0 + orow;
    const int cq = (lane & 3) * 2;
    const int pxq = lane >> 2;
#pragma unroll
    for (int mt = 0; mt < 2; ++mt) {
#pragma unroll
        for (int half = 0; half < 2; ++half) {
            int px = pxl + mt * 16 + pxq + half * 8;
            float* dst = g_h + (((size_t)(b * HW) + y) * HW + px) * CC;
#pragma unroll
            for (int nt = 0; nt < 8; ++nt) {
                int co = nt * 8 + cq;
                float a0 = acc[mt][nt][half * 2 + 0] + sbias[co];
                float a1 = acc[mt][nt][half * 2 + 1] + sbias[co + 1];
                a0 = a0 > 0.f ? a0 : 0.02f * a0;
                a1 = a1 > 0.f ? a1 : 0.02f * a1;
                *reinterpret_cast<float2*>(dst + co) = make_float2(a0, a1);
            }
        }
    }
}

// ============================================================================
// Gather + FC v5: block per k, warp per 4 b's. pos staged to smem once
// (coalesced) so h-prefetch chain has no global pos dependency; depth-2.
// ============================================================================
__global__ __launch_bounds__(256) void gather_fc_kernel(
    const int* __restrict__ pos,     // [K][B][L][2] (x, y)
    const float* __restrict__ pw,    // [24][768]
    const float* __restrict__ pb,    // [24]
    float* __restrict__ out)         // [K][B][24]
{
    __shared__ float wsm[384 * 26];  // 39,936 B
    __shared__ int2 psm[BBATCH * LL];// 3,072 B

    const int t = threadIdx.x;
    const int lane = t & 31;
    const int w = t >> 5;
    const int k = blockIdx.x;
    const int b0 = w * 4;

    // stage this k's positions (coalesced)
    {
        const int2* __restrict__ pos2 = reinterpret_cast<const int2*>(pos) + k * (BBATCH * LL);
        for (int i = t; i < BBATCH * LL; i += 256) psm[i] = pos2[i];
    }

    unsigned long long acc[4][12];
#pragma unroll
    for (int bi = 0; bi < 4; ++bi)
#pragma unroll
        for (int op = 0; op < 12; ++op) acc[bi][op] = 0ULL;

    float hbuf[3][8];

    for (int half = 0; half < 2; ++half) {
        __syncthreads();
        for (int i = t; i < 24 * 384; i += 256) {
            int o = i / 384;
            int jl = i - o * 384;
            wsm[jl * 26 + o] = pw[o * 768 + half * 384 + jl];
        }
        __syncthreads();   // also covers psm on first iteration

        // prefetch blocks 0 and 1
#pragma unroll
        for (int pp0 = 0; pp0 < 2; ++pp0) {
            const int l = half * 6 + pp0;
#pragma unroll
            for (int bi = 0; bi < 4; ++bi) {
                const int b = b0 + bi;
                int2 pp = psm[b * LL + l];
                int px = pp.x < 0 ? 0 : (pp.x > 127 ? 127 : pp.x);
                int py = pp.y < 0 ? 0 : (pp.y > 127 ? 127 : pp.y);
                const float* hp = &g_h[(((size_t)(b * HW) + py) * HW + px) * CC + lane];
                hbuf[pp0][bi]     = hp[0];
                hbuf[pp0][4 + bi] = hp[32];
            }
        }

#pragma unroll
        for (int p = 0; p < 6; ++p) {
            if (p < 4) {
                const int l = half * 6 + p + 2;
                const int slot = (p + 2) % 3;
#pragma unroll
                for (int bi = 0; bi < 4; ++bi) {
                    const int b = b0 + bi;
                    int2 pp = psm[b * LL + l];
                    int px = pp.x < 0 ? 0 : (pp.x > 127 ? 127 : pp.x);
                    int py = pp.y < 0 ? 0 : (pp.y > 127 ? 127 : pp.y);
                    const float* hp = &g_h[(((size_t)(b * HW) + py) * HW + px) * CC + lane];
                    hbuf[slot][bi]     = hp[0];
                    hbuf[slot][4 + bi] = hp[32];
                }
            }
            const int slot = p % 3;
#pragma unroll
            for (int jj = 0; jj < 2; ++jj) {
                const int j24 = 2 * p + jj;
                const float2* wrow =
                    reinterpret_cast<const float2*>(&wsm[(j24 * 32 + lane) * 26]);
                float2 wv[12];
#pragma unroll
                for (int op = 0; op < 12; ++op) wv[op] = wrow[op];
#pragma unroll
                for (int bi = 0; bi < 4; ++bi) {
                    float hv = hbuf[slot][jj * 4 + bi];
                    unsigned long long hv2 = pack2(hv, hv);
#pragma unroll
                    for (int op = 0; op < 12; ++op)
                        acc[bi][op] = ffma2(pack2(wv[op].x, wv[op].y), hv2, acc[bi][op]);
                }
            }
        }
    }

    // butterfly reduce over lanes (packed f32x2 adds)
#pragma unroll
    for (int bi = 0; bi < 4; ++bi)
#pragma unroll
        for (int op = 0; op < 12; ++op) {
            unsigned long long v = acc[bi][op];
#pragma unroll
            for (int m = 16; m > 0; m >>= 1) {
                double o = __shfl_xor_sync(0xffffffffu, __longlong_as_double((long long)v), m);
                v = addf2(v, (unsigned long long)__double_as_longlong(o));
            }
            acc[bi][op] = v;
        }

#pragma unroll
    for (int bi = 0; bi < 4; ++bi) {
#pragma unroll
        for (int op = 0; op < 12; ++op) {
            if (lane == op) {
                float a0, a1;
                unpack2(acc[bi][op], a0, a1);
                float2 o2;
                o2.x = a0 + pb[2 * op];
                o2.y = a1 + pb[2 * op + 1];
                *reinterpret_cast<float2*>(&out[(size_t)((k * BBATCH + b0 + bi) * OO) + 2 * op]) = o2;
            }
        }
    }
}

// ============================================================================
extern "C" void kernel_launch(void* const* d_in, const int* in_sizes, int n_in,
                              void* d_out, int out_size) {
    const float* x   = (const float*)d_in[0];   // [32][64][128][128]
    const int*   pos = (const int*)  d_in[1];   // [1000][32][12][2]
    const float* cw  = (const float*)d_in[2];   // [64][64][3][3]
    const float* cb  = (const float*)d_in[3];   // [64]
    const float* pw  = (const float*)d_in[4];   // [24][768]
    const float* pb  = (const float*)d_in[5];   // [24]
    float* out = (float*)d_out;                 // [1000][32][24]

    cudaFuncSetAttribute(conv_tc_kernel, cudaFuncAttributeMaxDynamicSharedMemorySize, SM_TOT);

    conv_tc_kernel<<<dim3(HW / 2, BBATCH), 256, SM_TOT>>>(x, cw, cb);
    gather_fc_kernel<<<KK, 256>>>(pos, pw, pb, out);
}